// round 15
// baseline (speedup 1.0000x reference)
#include <cuda_runtime.h>
#include <cuda_fp16.h>
#include <math.h>
#include <stdint.h>

// Problem constants
#define B_ 4
#define S_ 2048
#define H_ 1024
#define K_ 64
#define NH_ 16
#define L_ 2
#define FF_ 2730
#define FF2_ 5460   // 2*FF (interleaved u/g)
#define FFP_ 2736   // padded FF (16B-aligned fp16 rows)

// ---------------- scratch (device globals) ----------
__device__ float g_x[256 * 1024];
__device__ float g_qkv[256 * 3072];
__device__ float g_q[8192 * 1024];
__device__ float g_kk[256 * 1024];
__device__ float g_vv[256 * 1024];
__device__ int   g_sidx[256];

__device__ __half g_w16[46149632];          // all converted weights + token16
__device__ __half g_q16[8192 * 1024];
__device__ __half g_ph[256 * 1024];
__device__ __half g_patt[256 * 1024];
__device__ __half g_uhs[256 * FFP_];
__device__ __half g_proc16[256 * 1024];
__device__ __half g_dec16[8192 * 1024];
__device__ __half g_y1n16[8192 * 1024];
__device__ __half g_uhb[8192L * FFP_];

// ================= helpers =================
__device__ __forceinline__ uint32_t smem_u32(const void* p) {
    uint32_t a;
    asm("{ .reg .u64 t; cvta.to.shared.u64 t, %1; cvt.u32.u64 %0, t; }" : "=r"(a) : "l"(p));
    return a;
}

#define HROWB 144   // bytes per smem row: 64 halves (128B) + 16B pad -> conflict-free LDSM

// fp16 K-chunk (64) tile loader
template <int ROWS, int THREADS>
__device__ __forceinline__ void tile_load_h(const __half* __restrict__ src, int rowBase, int rowLim,
                                            int lda, int Kd, int k0, uint32_t sdst, int tid) {
    if (k0 + 64 <= Kd) {
        #pragma unroll
        for (int t = tid; t < ROWS * 8; t += THREADS) {
            int r = t >> 3, ch = t & 7;
            uint32_t d = sdst + (uint32_t)(r * HROWB + ch * 16);
            int gr = rowBase + r;
            if (gr < rowLim) {
                const __half* g = src + (long)gr * lda + k0 + ch * 8;
                asm volatile("cp.async.cg.shared.global [%0], [%1], 16;" :: "r"(d), "l"(g));
            } else {
                asm volatile("st.shared.v4.b32 [%0], {%1,%1,%1,%1};" :: "r"(d), "r"(0));
            }
        }
    } else {
        #pragma unroll
        for (int t = tid; t < ROWS * 64; t += THREADS) {
            int r = t >> 6, k = t & 63;
            int gr = rowBase + r, gk = k0 + k;
            uint16_t v = 0;
            if (gr < rowLim && gk < Kd) v = __half_as_ushort(src[(long)gr * lda + gk]);
            uint32_t d = sdst + (uint32_t)(r * HROWB + k * 2);
            asm volatile("st.shared.u16 [%0], %1;" :: "r"(d), "h"(v));
        }
    }
}

#define CP_COMMIT() asm volatile("cp.async.commit_group;" ::: "memory")
#define CP_WAIT1()  asm volatile("cp.async.wait_group 1;" ::: "memory")
#define CP_WAIT0()  asm volatile("cp.async.wait_group 0;" ::: "memory")

#define MMA_F16(acc, a, b) \
    asm volatile("mma.sync.aligned.m16n8k16.row.col.f32.f16.f16.f32 " \
        "{%0,%1,%2,%3}, {%4,%5,%6,%7}, {%8,%9}, {%0,%1,%2,%3};" \
        : "+f"((acc)[0]), "+f"((acc)[1]), "+f"((acc)[2]), "+f"((acc)[3]) \
        : "r"((a)[0]), "r"((a)[1]), "r"((a)[2]), "r"((a)[3]), "r"((b)[0]), "r"((b)[1]))

#define LDSM_X4(r0, r1, r2, r3, addr) \
    asm volatile("ldmatrix.sync.aligned.m8n8.x4.shared.b16 {%0,%1,%2,%3}, [%4];" \
        : "=r"(r0), "=r"(r1), "=r"(r2), "=r"(r3) : "r"(addr))

// epilogue modes:
// 0 = f32 store (+bias); 1 = f32 addC (+bias); 2 = f16 store (ldD, +bias);
// 4 = paired swiglu: acc pair (u,g) at cols (n, n+1) -> silu(u)*g stored f16 at col n/2 (ldD)
__device__ __forceinline__ void epi_pair(int mode, void* D, int ldD,
                                         const float* bias, int N, long m, int n,
                                         float vx, float vy) {
    if (n >= N) return;
    if (bias) { vx += bias[n]; vy += bias[n + 1]; }
    if (mode == 0) {
        *(float2*)((float*)D + m * N + n) = make_float2(vx, vy);
    } else if (mode == 1) {
        float2* cp = (float2*)((float*)D + m * N + n);
        float2 o = *cp;
        *cp = make_float2(vx + o.x, vy + o.y);
    } else if (mode == 2) {
        *(__half2*)((__half*)D + m * ldD + n) = __floats2half2_rn(vx, vy);
    } else {
        float h = (vx / (1.f + expf(-vx))) * vy;
        *((__half*)D + m * ldD + (n >> 1)) = __float2half_rn(h);
    }
}

// ================= big GEMM: 128x128 tile, BK=64, 8 warps (2x4), warp 64x32 ==
#define BIG_TILE_B (128 * HROWB)
#define BIG_STAGE_B (2 * BIG_TILE_B)
#define BIG_SMEM_BYTES (3 * BIG_STAGE_B)

__global__ void __launch_bounds__(256) gemm_h16(const __half* __restrict__ A, int lda,
                                                const __half* __restrict__ Bw, int ldb,
                                                const float* __restrict__ bias, void* __restrict__ D,
                                                int ldD, int M, int N, int Kd, int mode) {
    extern __shared__ uint32_t smu[];
    const uint32_t sbase = smem_u32(smu);
    const int tid = threadIdx.x;
    const int wid = tid >> 5, lane = tid & 31;
    const int wm = wid & 1, wn = wid >> 1;
    const int bm = blockIdx.y * 128, bn = blockIdx.x * 128;
    const int lr = lane >> 2, lc = lane & 3;
    const uint32_t lrow = (lane & 15), lhi = (lane >> 4) << 4;

    float acc[4][4][4];
    #pragma unroll
    for (int i = 0; i < 4; i++)
        #pragma unroll
        for (int j = 0; j < 4; j++)
            #pragma unroll
            for (int e = 0; e < 4; e++) acc[i][j][e] = 0.f;

    const int NC = (Kd + 63) / 64;

    tile_load_h<128, 256>(A, bm, M, lda, Kd, 0, sbase, tid);
    tile_load_h<128, 256>(Bw, bn, N, ldb, Kd, 0, sbase + BIG_TILE_B, tid);
    CP_COMMIT();
    if (NC > 1) {
        tile_load_h<128, 256>(A, bm, M, lda, Kd, 64, sbase + BIG_STAGE_B, tid);
        tile_load_h<128, 256>(Bw, bn, N, ldb, Kd, 64, sbase + BIG_STAGE_B + BIG_TILE_B, tid);
        CP_COMMIT();
    }

    for (int c = 0; c < NC; c++) {
        if (c + 1 < NC) CP_WAIT1(); else CP_WAIT0();
        __syncthreads();
        if (c + 2 < NC) {
            uint32_t soff = sbase + (uint32_t)(((c + 2) % 3) * BIG_STAGE_B);
            tile_load_h<128, 256>(A, bm, M, lda, Kd, (c + 2) * 64, soff, tid);
            tile_load_h<128, 256>(Bw, bn, N, ldb, Kd, (c + 2) * 64, soff + BIG_TILE_B, tid);
            CP_COMMIT();
        }
        const uint32_t abase = sbase + (uint32_t)((c % 3) * BIG_STAGE_B);
        const uint32_t bbase = abase + BIG_TILE_B;
        #pragma unroll
        for (int ks = 0; ks < 4; ks++) {
            uint32_t afr[4][4], bfr[4][2];
            #pragma unroll
            for (int mi = 0; mi < 4; mi++) {
                uint32_t ad = abase + (wm * 64 + mi * 16 + lrow) * HROWB + ks * 32 + lhi;
                LDSM_X4(afr[mi][0], afr[mi][1], afr[mi][2], afr[mi][3], ad);
            }
            #pragma unroll
            for (int p = 0; p < 2; p++) {
                uint32_t e0, o0, e1, o1;
                uint32_t bd = bbase + (wn * 32 + p * 16 + lrow) * HROWB + ks * 32 + lhi;
                LDSM_X4(e0, o0, e1, o1, bd);
                bfr[2 * p][0] = e0; bfr[2 * p][1] = e1;
                bfr[2 * p + 1][0] = o0; bfr[2 * p + 1][1] = o1;
            }
            #pragma unroll
            for (int mi = 0; mi < 4; mi++)
                #pragma unroll
                for (int ni = 0; ni < 4; ni++)
                    MMA_F16(acc[mi][ni], afr[mi], bfr[ni]);
        }
    }

    #pragma unroll
    for (int mi = 0; mi < 4; mi++) {
        #pragma unroll
        for (int ni = 0; ni < 4; ni++) {
            long m0 = bm + wm * 64 + mi * 16 + lr;
            int n0 = bn + wn * 32 + ni * 8 + 2 * lc;
            epi_pair(mode, D, ldD, bias, N, m0, n0, acc[mi][ni][0], acc[mi][ni][1]);
            epi_pair(mode, D, ldD, bias, N, m0 + 8, n0, acc[mi][ni][2], acc[mi][ni][3]);
        }
    }
}

// ================= small GEMM: 64x64 tile, BK=64, 4 warps (2x2) =============
#define SM_TILE_B (64 * HROWB)
#define SM_STAGE_B (2 * SM_TILE_B)
#define SM_SMEM_BYTES (3 * SM_STAGE_B)

__global__ void __launch_bounds__(128) gemm_h16_s(const __half* __restrict__ A, int lda,
                                                  const __half* __restrict__ Bw, int ldb,
                                                  const float* __restrict__ bias, void* __restrict__ D,
                                                  int ldD, int M, int N, int Kd, int mode) {
    extern __shared__ uint32_t smu[];
    const uint32_t sbase = smem_u32(smu);
    const int tid = threadIdx.x;
    const int wid = tid >> 5, lane = tid & 31;
    const int wm = wid & 1, wn = wid >> 1;
    const int bm = blockIdx.y * 64, bn = blockIdx.x * 64;
    const int lr = lane >> 2, lc = lane & 3;
    const uint32_t lrow = (lane & 15), lhi = (lane >> 4) << 4;

    float acc[2][4][4];
    #pragma unroll
    for (int i = 0; i < 2; i++)
        #pragma unroll
        for (int j = 0; j < 4; j++)
            #pragma unroll
            for (int e = 0; e < 4; e++) acc[i][j][e] = 0.f;

    const int NC = (Kd + 63) / 64;

    tile_load_h<64, 128>(A, bm, M, lda, Kd, 0, sbase, tid);
    tile_load_h<64, 128>(Bw, bn, N, ldb, Kd, 0, sbase + SM_TILE_B, tid);
    CP_COMMIT();
    if (NC > 1) {
        tile_load_h<64, 128>(A, bm, M, lda, Kd, 64, sbase + SM_STAGE_B, tid);
        tile_load_h<64, 128>(Bw, bn, N, ldb, Kd, 64, sbase + SM_STAGE_B + SM_TILE_B, tid);
        CP_COMMIT();
    }

    for (int c = 0; c < NC; c++) {
        if (c + 1 < NC) CP_WAIT1(); else CP_WAIT0();
        __syncthreads();
        if (c + 2 < NC) {
            uint32_t soff = sbase + (uint32_t)(((c + 2) % 3) * SM_STAGE_B);
            tile_load_h<64, 128>(A, bm, M, lda, Kd, (c + 2) * 64, soff, tid);
            tile_load_h<64, 128>(Bw, bn, N, ldb, Kd, (c + 2) * 64, soff + SM_TILE_B, tid);
            CP_COMMIT();
        }
        const uint32_t abase = sbase + (uint32_t)((c % 3) * SM_STAGE_B);
        const uint32_t bbase = abase + SM_TILE_B;
        #pragma unroll
        for (int ks = 0; ks < 4; ks++) {
            uint32_t afr[2][4], bfr[4][2];
            #pragma unroll
            for (int mi = 0; mi < 2; mi++) {
                uint32_t ad = abase + (wm * 32 + mi * 16 + lrow) * HROWB + ks * 32 + lhi;
                LDSM_X4(afr[mi][0], afr[mi][1], afr[mi][2], afr[mi][3], ad);
            }
            #pragma unroll
            for (int p = 0; p < 2; p++) {
                uint32_t e0, o0, e1, o1;
                uint32_t bd = bbase + (wn * 32 + p * 16 + lrow) * HROWB + ks * 32 + lhi;
                LDSM_X4(e0, o0, e1, o1, bd);
                bfr[2 * p][0] = e0; bfr[2 * p][1] = e1;
                bfr[2 * p + 1][0] = o0; bfr[2 * p + 1][1] = o1;
            }
            #pragma unroll
            for (int mi = 0; mi < 2; mi++)
                #pragma unroll
                for (int ni = 0; ni < 4; ni++)
                    MMA_F16(acc[mi][ni], afr[mi], bfr[ni]);
        }
    }

    #pragma unroll
    for (int mi = 0; mi < 2; mi++) {
        #pragma unroll
        for (int ni = 0; ni < 4; ni++) {
            long m0 = bm + wm * 32 + mi * 16 + lr;
            int n0 = bn + wn * 32 + ni * 8 + 2 * lc;
            if (m0 < M) {
                epi_pair(mode, D, ldD, bias, N, m0, n0, acc[mi][ni][0], acc[mi][ni][1]);
                epi_pair(mode, D, ldD, bias, N, m0 + 8, n0, acc[mi][ni][2], acc[mi][ni][3]);
            }
        }
    }
}

// ---------------- conversions ----------------
__global__ void convert_f2h4(const float4* __restrict__ src, __half2* __restrict__ dst, long n4) {
    long stride = (long)gridDim.x * blockDim.x;
    for (long i = (long)blockIdx.x * blockDim.x + threadIdx.x; i < n4; i += stride) {
        float4 v = src[i];
        dst[2 * i]     = __floats2half2_rn(v.x, v.y);
        dst[2 * i + 1] = __floats2half2_rn(v.z, v.w);
    }
}
__global__ void convert_f2h_pad2(const float2* __restrict__ src, __half2* __restrict__ dst,
                                 int rows, int Kc2, int ldd2) {
    int r = blockIdx.x;
    const float2* srow = src + (long)r * Kc2;
    __half2* drow = dst + (long)r * ldd2;
    for (int c = threadIdx.x; c < Kc2; c += blockDim.x) {
        float2 v = srow[c];
        drow[c] = __floats2half2_rn(v.x, v.y);
    }
}
// interleave: dst row 2j = w1 row j, dst row 2j+1 = w3 row j.  K = 1024
__global__ void convert_inter(const float4* __restrict__ w1, const float4* __restrict__ w3,
                              __half2* __restrict__ dst, long rows) {
    long n = rows * 256;
    long stride = (long)gridDim.x * blockDim.x;
    for (long i = (long)blockIdx.x * blockDim.x + threadIdx.x; i < n; i += stride) {
        long r = i >> 8;
        int c = (int)(i & 255);
        float4 a = w1[i];
        float4 b = w3[i];
        __half2* d1 = dst + (2 * r) * 512 + 2 * c;
        __half2* d3 = dst + (2 * r + 1) * 512 + 2 * c;
        d1[0] = __floats2half2_rn(a.x, a.y);
        d1[1] = __floats2half2_rn(a.z, a.w);
        d3[0] = __floats2half2_rn(b.x, b.y);
        d3[1] = __floats2half2_rn(b.z, b.w);
    }
}

// ---------------- block reduce ----------------
__device__ __forceinline__ float blockReduceSum(float v) {
    __shared__ float sh[33];
    int lane = threadIdx.x & 31, wid = threadIdx.x >> 5;
    #pragma unroll
    for (int o = 16; o; o >>= 1) v += __shfl_xor_sync(0xFFFFFFFFu, v, o);
    if (lane == 0) sh[wid] = v;
    __syncthreads();
    int nw = blockDim.x >> 5;
    v = (threadIdx.x < nw) ? sh[lane] : 0.f;
    if (wid == 0) {
        #pragma unroll
        for (int o = 16; o; o >>= 1) v += __shfl_xor_sync(0xFFFFFFFFu, v, o);
        if (lane == 0) sh[32] = v;
    }
    __syncthreads();
    return sh[32];
}

// ---------------- sort + gather / unsort ----------------
__global__ void sort_gather_kernel(const float* __restrict__ cw,
                                   const float* __restrict__ repr,
                                   float* __restrict__ x, int* __restrict__ sidx) {
    int b = blockIdx.x, tid = threadIdx.x;
    __shared__ float w[64];
    __shared__ int pos[64];
    if (tid < 64) w[tid] = cw[b * 64 + tid];
    __syncthreads();
    if (tid < 64) {
        float wi = w[tid];
        int r = 0;
        for (int j = 0; j < 64; j++) {
            float wj = w[j];
            if (wj > wi || (wj == wi && j < tid)) r++;
        }
        pos[r] = tid;
        sidx[b * 64 + r] = tid;
    }
    __syncthreads();
    for (int t = tid; t < 64 * 256; t += blockDim.x) {
        int k = t >> 8, c4 = t & 255;
        const float4* s = (const float4*)(repr + ((long)b * 64 + pos[k]) * 1024) + c4;
        *((float4*)(x + ((long)b * 64 + k) * 1024) + c4) = *s;
    }
}

__global__ void unsort_h_kernel(const float* __restrict__ x, const int* __restrict__ sidx,
                                __half* __restrict__ proc) {
    int b = blockIdx.x, tid = threadIdx.x;
    __shared__ int pos[64];
    if (tid < 64) pos[tid] = sidx[b * 64 + tid];
    __syncthreads();
    for (int t = tid; t < 64 * 256; t += blockDim.x) {
        int k = t >> 8, c4 = t & 255;
        float4 v = *((const float4*)(x + ((long)b * 64 + k) * 1024) + c4);
        __half2* d = (__half2*)(proc + ((long)b * 64 + pos[k]) * 1024) + 2 * c4;
        d[0] = __floats2half2_rn(v.x, v.y);
        d[1] = __floats2half2_rn(v.z, v.w);
    }
}

// ---------------- RMS (fp32 in -> fp16 out) ----------------
__global__ void rms16_kernel(const float* __restrict__ x, const float* __restrict__ w,
                             __half* __restrict__ out) {
    long row = blockIdx.x;
    const float* xr = x + row * H_;
    float s = 0.f;
    for (int i = threadIdx.x; i < H_; i += blockDim.x) { float v = xr[i]; s += v * v; }
    float tot = blockReduceSum(s);
    float scale = rsqrtf(tot * (1.0f / H_) + 1e-6f);
    for (int i = threadIdx.x; i < H_; i += blockDim.x)
        out[row * H_ + i] = __float2half_rn(xr[i] * scale * w[i]);
}

// fused: y1 = rms(a+b, w1) -> out (fp32); y2 = rms(y1, w2) -> y16 (fp16)
__global__ void add_rms2_kernel(const float* __restrict__ a, const float* __restrict__ bsrc,
                                const float* __restrict__ w1, const float* __restrict__ w2,
                                float* __restrict__ out, __half* __restrict__ y16) {
    long row = blockIdx.x;
    __shared__ float buf[H_];
    float s = 0.f;
    for (int i = threadIdx.x; i < H_; i += blockDim.x) {
        float v = a[row * H_ + i] + bsrc[row * H_ + i];
        buf[i] = v;
        s += v * v;
    }
    float tot = blockReduceSum(s);
    float sc1 = rsqrtf(tot * (1.0f / H_) + 1e-6f);
    float s2 = 0.f;
    for (int i = threadIdx.x; i < H_; i += blockDim.x) {
        float y1 = buf[i] * sc1 * w1[i];
        out[row * H_ + i] = y1;
        s2 += y1 * y1;
    }
    float tot2 = blockReduceSum(s2);
    float sc2 = rsqrtf(tot2 * (1.0f / H_) + 1e-6f);
    for (int i = threadIdx.x; i < H_; i += blockDim.x) {
        float y1 = buf[i] * sc1 * w1[i];
        y16[row * H_ + i] = __float2half_rn(y1 * sc2 * w2[i]);
    }
}

// ---------------- cascade self-attention (causal, K=64, d=64) --------------
#define KST 65
#define CASC_SMEM (4 * 64 * KST * 4)
__global__ void casc_attn_kernel(const float* __restrict__ qkv, __half* __restrict__ att) {
    int h = blockIdx.x, b = blockIdx.y;
    extern __shared__ float cs[];
    float* Qs = cs;
    float* Ks = cs + 64 * KST;
    float* Vs = cs + 2 * 64 * KST;
    float* Ps = cs + 3 * 64 * KST;
    const float* base = qkv + (long)b * 64 * 3072;
    int tid = threadIdx.x;
    for (int t = tid; t < 4096; t += 256) {
        int r = t >> 6, j = t & 63;
        const float* src = base + r * 3072 + h * 64 + j;
        Qs[r * KST + j] = src[0];
        Ks[r * KST + j] = src[1024];
        Vs[r * KST + j] = src[2048];
    }
    __syncthreads();
    int i = tid >> 2;
    int jg = (tid & 3) * 16;
    float sc[16];
    #pragma unroll
    for (int jj = 0; jj < 16; jj++) sc[jj] = 0.f;
    for (int k = 0; k < 64; k++) {
        float qv = Qs[i * KST + k];
        #pragma unroll
        for (int jj = 0; jj < 16; jj++) sc[jj] = fmaf(qv, Ks[(jg + jj) * KST + k], sc[jj]);
    }
    float mx = -1e30f;
    #pragma unroll
    for (int jj = 0; jj < 16; jj++) {
        int j = jg + jj;
        sc[jj] = (j <= i) ? sc[jj] * 0.125f : -1e30f;
        mx = fmaxf(mx, sc[jj]);
    }
    mx = fmaxf(mx, __shfl_xor_sync(0xFFFFFFFFu, mx, 1));
    mx = fmaxf(mx, __shfl_xor_sync(0xFFFFFFFFu, mx, 2));
    float e[16];
    float sum = 0.f;
    #pragma unroll
    for (int jj = 0; jj < 16; jj++) {
        int j = jg + jj;
        e[jj] = (j <= i) ? expf(sc[jj] - mx) : 0.f;
        sum += e[jj];
    }
    sum += __shfl_xor_sync(0xFFFFFFFFu, sum, 1);
    sum += __shfl_xor_sync(0xFFFFFFFFu, sum, 2);
    float inv = 1.f / sum;
    #pragma unroll
    for (int jj = 0; jj < 16; jj++) Ps[i * KST + jg + jj] = e[jj] * inv;
    __syncthreads();
    float o[16];
    #pragma unroll
    for (int jj = 0; jj < 16; jj++) o[jj] = 0.f;
    for (int k = 0; k < 64; k++) {
        float p = Ps[i * KST + k];
        #pragma unroll
        for (int jj = 0; jj < 16; jj++) o[jj] = fmaf(p, Vs[k * KST + jg + jj], o[jj]);
    }
    __half* orow = att + (long)(b * 64 + i) * 1024 + h * 64;
    #pragma unroll
    for (int jj = 0; jj < 16; jj++) orow[jg + jj] = __float2half_rn(o[jj]);
}

// ---------------- decoder cross-attention (Q fp16) ------------------------
__global__ void dec_attn_kernel(const __half* __restrict__ Qh, const float* __restrict__ Kc,
                                const float* __restrict__ Vc, __half* __restrict__ O) {
    int h = blockIdx.y, b = blockIdx.z;
    __shared__ float Ks[64][65];
    __shared__ float Vs[64][65];
    __shared__ float Qs[32][68];
    __shared__ float Pw[8][64];
    int tid = threadIdx.x;
    int s0 = blockIdx.x * 32;
    for (int t = tid; t < 4096; t += 256) {
        int r = t >> 6, j = t & 63;
        Ks[r][j] = Kc[(long)(b * 64 + r) * 1024 + h * 64 + j];
        Vs[r][j] = Vc[(long)(b * 64 + r) * 1024 + h * 64 + j];
    }
    for (int t = tid; t < 1024; t += 256) {
        int r = t >> 5, j2 = (t & 31) * 2;
        __half2 v = *(const __half2*)(Qh + ((long)b * S_ + s0 + r) * 1024 + h * 64 + j2);
        Qs[r][j2] = __half2float(v.x);
        Qs[r][j2 + 1] = __half2float(v.y);
    }
    __syncthreads();
    int warp = tid >> 5, lane = tid & 31;
    for (int qi = 0; qi < 4; qi++) {
        int lrq = warp * 4 + qi;
        int s = s0 + lrq;
        int lim = s / 32 + 1;
        if (lim > 63) lim = 63;
        float sc0 = 0.f, sc1 = 0.f;
        for (int k = 0; k < 64; k++) {
            float qv = Qs[lrq][k];
            sc0 = fmaf(qv, Ks[lane][k], sc0);
            sc1 = fmaf(qv, Ks[lane + 32][k], sc1);
        }
        sc0 *= 0.125f;
        sc1 *= 0.125f;
        bool a0 = lane <= lim, a1 = (lane + 32) <= lim;
        float m = fmaxf(a0 ? sc0 : -1e30f, a1 ? sc1 : -1e30f);
        #pragma unroll
        for (int o = 16; o; o >>= 1) m = fmaxf(m, __shfl_xor_sync(0xFFFFFFFFu, m, o));
        float e0 = a0 ? expf(sc0 - m) : 0.f;
        float e1 = a1 ? expf(sc1 - m) : 0.f;
        float sum = e0 + e1;
        #pragma unroll
        for (int o = 16; o; o >>= 1) sum += __shfl_xor_sync(0xFFFFFFFFu, sum, o);
        float inv = 1.f / sum;
        Pw[warp][lane] = e0 * inv;
        Pw[warp][lane + 32] = e1 * inv;
        __syncwarp();
        float o0 = 0.f, o1 = 0.f;
        for (int k = 0; k <= lim; k++) {
            float p = Pw[warp][k];
            o0 = fmaf(p, Vs[k][lane], o0);
            o1 = fmaf(p, Vs[k][lane + 32], o1);
        }
        __half* orow = O + ((long)b * S_ + s) * 1024 + h * 64;
        orow[lane] = __float2half_rn(o0);
        orow[lane + 32] = __float2half_rn(o1);
        __syncwarp();
    }
}

// ---------------- host launch ---------------------------------------------
static void gemm_h(cudaStream_t st, const __half* A, int lda, const __half* Bw, int ldb,
                   const float* bias, void* D, int ldD, int M, int N, int Kd, int mode) {
    if (M <= 256) {
        dim3 g((N + 63) / 64, (M + 63) / 64);
        gemm_h16_s<<<g, 128, SM_SMEM_BYTES, st>>>(A, lda, Bw, ldb, bias, D, ldD, M, N, Kd, mode);
    } else {
        dim3 g((N + 127) / 128, (M + 127) / 128);
        gemm_h16<<<g, 256, BIG_SMEM_BYTES, st>>>(A, lda, Bw, ldb, bias, D, ldD, M, N, Kd, mode);
    }
}

extern "C" void kernel_launch(void* const* d_in, const int* in_sizes, int n_in,
                              void* d_out, int out_size) {
    const float* token        = (const float*)d_in[0];
    const float* chunk_repr   = (const float*)d_in[1];
    const float* chunk_w      = (const float*)d_in[2];
    const float* casc_norm1   = (const float*)d_in[3];
    const float* casc_qkv     = (const float*)d_in[4];
    const float* casc_o       = (const float*)d_in[5];
    const float* casc_norm2   = (const float*)d_in[6];
    const float* casc_w1      = (const float*)d_in[7];
    const float* casc_w2      = (const float*)d_in[8];
    const float* casc_w3      = (const float*)d_in[9];
    const float* dec_in_w     = (const float*)d_in[10];
    const float* dec_in_b     = (const float*)d_in[11];
    const float* dec_out_w    = (const float*)d_in[12];
    const float* dec_out_b    = (const float*)d_in[13];
    const float* dec_norm_w   = (const float*)d_in[14];
    const float* dec_ffn_norm = (const float*)d_in[15];
    const float* dec_w1       = (const float*)d_in[16];
    const float* dec_w2       = (const float*)d_in[17];
    const float* dec_w3       = (const float*)d_in[18];
    float* out = (float*)d_out;

    cudaFuncSetAttribute(gemm_h16, cudaFuncAttributeMaxDynamicSharedMemorySize, BIG_SMEM_BYTES);
    cudaFuncSetAttribute(gemm_h16_s, cudaFuncAttributeMaxDynamicSharedMemorySize, SM_SMEM_BYTES);
    cudaFuncSetAttribute(casc_attn_kernel, cudaFuncAttributeMaxDynamicSharedMemorySize, CASC_SMEM);

    float *px, *pqkv, *pq, *pkk, *pvv;
    int* psidx;
    __half *pw, *pq16, *pph, *ppatt, *puhs, *pproc16, *pdec16, *py1n16, *puhb;
    cudaGetSymbolAddress((void**)&px, g_x);
    cudaGetSymbolAddress((void**)&pqkv, g_qkv);
    cudaGetSymbolAddress((void**)&pq, g_q);
    cudaGetSymbolAddress((void**)&pkk, g_kk);
    cudaGetSymbolAddress((void**)&pvv, g_vv);
    cudaGetSymbolAddress((void**)&psidx, g_sidx);
    cudaGetSymbolAddress((void**)&pw, g_w16);
    cudaGetSymbolAddress((void**)&pq16, g_q16);
    cudaGetSymbolAddress((void**)&pph, g_ph);
    cudaGetSymbolAddress((void**)&ppatt, g_patt);
    cudaGetSymbolAddress((void**)&puhs, g_uhs);
    cudaGetSymbolAddress((void**)&pproc16, g_proc16);
    cudaGetSymbolAddress((void**)&pdec16, g_dec16);
    cudaGetSymbolAddress((void**)&py1n16, g_y1n16);
    cudaGetSymbolAddress((void**)&puhb, g_uhb);

    // ---- fp16 weight layout (interleaved w1/w3) ----
    const long o_cqkv = 0;
    const long o_co   = o_cqkv + 2L * 3072 * 1024;
    const long o_cw13 = o_co   + 2L * 1024 * 1024;
    const long o_cw2  = o_cw13 + 2L * FF2_ * 1024;
    const long o_din  = o_cw2  + 2L * 1024 * FFP_;
    const long o_dout = o_din  + 3L * 1024 * 1024;
    const long o_dw13 = o_dout + 1024L * 1024;
    const long o_dw2  = o_dw13 + (long)FF2_ * 1024;
    const long o_tok  = o_dw2  + 1024L * FFP_;
    const __half* tok16 = pw + o_tok;

    // ---- stream fork ----
    cudaStream_t s1;
    cudaStreamCreateWithFlags(&s1, cudaStreamNonBlocking);
    cudaEvent_t ev0, ev1;
    cudaEventCreateWithFlags(&ev0, cudaEventDisableTiming);
    cudaEventCreateWithFlags(&ev1, cudaEventDisableTiming);
    cudaEventRecord(ev0, 0);
    cudaStreamWaitEvent(s1, ev0, 0);

    // side stream: decoder prep + Q projection (fp16 out)
    convert_f2h4<<<2048, 256, 0, s1>>>((const float4*)token, (__half2*)(pw + o_tok), 8192L * 256);
    convert_f2h4<<<1024, 256, 0, s1>>>((const float4*)dec_in_w, (__half2*)(pw + o_din), 3L * 256 * 1024);
    convert_f2h4<<<512, 256, 0, s1>>>((const float4*)dec_out_w, (__half2*)(pw + o_dout), 256L * 1024);
    convert_inter<<<1024, 256, 0, s1>>>((const float4*)dec_w1, (const float4*)dec_w3,
                                        (__half2*)(pw + o_dw13), FF_);
    convert_f2h_pad2<<<1024, 256, 0, s1>>>((const float2*)dec_w2, (__half2*)(pw + o_dw2), 1024, FF_ / 2, FFP_ / 2);
    gemm_h(s1, tok16, 1024, pw + o_din, 1024, dec_in_b, pq16, 1024, B_ * S_, 1024, 1024, 2);  // Q proj fp16
    cudaEventRecord(ev1, s1);

    // main stream: cascade weights + cascade pipeline
    convert_f2h4<<<1024, 256>>>((const float4*)casc_qkv, (__half2*)(pw + o_cqkv), 2L * 3072 * 256);
    convert_f2h4<<<512, 256>>>((const float4*)casc_o, (__half2*)(pw + o_co), 2L * 256 * 1024);
    convert_inter<<<1024, 256>>>((const float4*)casc_w1, (const float4*)casc_w3,
                                 (__half2*)(pw + o_cw13), 2L * FF_);
    convert_f2h_pad2<<<2048, 256>>>((const float2*)casc_w2, (__half2*)(pw + o_cw2), 2 * 1024, FF_ / 2, FFP_ / 2);

    sort_gather_kernel<<<B_, 256>>>(chunk_w, chunk_repr, px, psidx);

    for (int l = 0; l < L_; l++) {
        rms16_kernel<<<256, 256>>>(px, casc_norm1 + (long)l * H_, pph);
        gemm_h(0, pph, 1024, pw + o_cqkv + (long)l * 3072 * 1024, 1024, nullptr, pqkv, 0, 256, 3072, 1024, 0);
        casc_attn_kernel<<<dim3(NH_, B_), 256, CASC_SMEM>>>(pqkv, ppatt);
        gemm_h(0, ppatt, 1024, pw + o_co + (long)l * 1024 * 1024, 1024, nullptr, px, 0, 256, 1024, 1024, 1);
        rms16_kernel<<<256, 256>>>(px, casc_norm2 + (long)l * H_, pph);
        gemm_h(0, pph, 1024, pw + o_cw13 + (long)l * FF2_ * 1024, 1024, nullptr, puhs, FFP_, 256, FF2_, 1024, 4);
        gemm_h(0, puhs, FFP_, pw + o_cw2 + (long)l * 1024 * FFP_, FFP_, nullptr, px, 0, 256, 1024, FF_, 1);
    }

    unsort_h_kernel<<<B_, 256>>>(px, psidx, pproc16);

    cudaStreamWaitEvent(0, ev1, 0);
    gemm_h(0, pproc16, 1024, pw + o_din + 1024L * 1024, 1024, dec_in_b + 1024, pkk, 0, 256, 1024, 1024, 0);
    gemm_h(0, pproc16, 1024, pw + o_din + 2L * 1024 * 1024, 1024, dec_in_b + 2048, pvv, 0, 256, 1024, 1024, 0);
    dec_attn_kernel<<<dim3(S_ / 32, NH_, B_), 256>>>(pq16, pkk, pvv, pdec16);
    gemm_h(0, pdec16, 1024, pw + o_dout, 1024, dec_out_b, pq, 0, B_ * S_, 1024, 1024, 0);     // out proj
    add_rms2_kernel<<<B_ * S_, 256>>>(token, pq, dec_norm_w, dec_ffn_norm, out, py1n16);
    gemm_h(0, py1n16, 1024, pw + o_dw13, 1024, nullptr, puhb, FFP_, B_ * S_, FF2_, 1024, 4);  // fused w1/w3+swiglu
    gemm_h(0, puhb, FFP_, pw + o_dw2, FFP_, nullptr, out, 0, B_ * S_, 1024, FF_, 1);          // y = y1 + ffn
}

// round 16
// speedup vs baseline: 1.0783x; 1.0783x over previous
#include <cuda_runtime.h>
#include <cuda_fp16.h>
#include <math.h>
#include <stdint.h>

// Problem constants
#define B_ 4
#define S_ 2048
#define H_ 1024
#define K_ 64
#define NH_ 16
#define L_ 2
#define FF_ 2730
#define FF2_ 5460   // 2*FF (interleaved u/g)
#define FFP_ 2736   // padded FF (16B-aligned fp16 rows)

// ---------------- scratch (device globals) ----------
__device__ float g_x[256 * 1024];
__device__ float g_qkv[256 * 3072];
__device__ float g_q[8192 * 1024];
__device__ float g_kk[256 * 1024];
__device__ float g_vv[256 * 1024];
__device__ int   g_sidx[256];

__device__ __half g_w16[46149632];          // all converted weights + token16
__device__ __half g_q16[8192 * 1024];
__device__ __half g_ph[256 * 1024];
__device__ __half g_patt[256 * 1024];
__device__ __half g_uhs[256 * FFP_];
__device__ __half g_proc16[256 * 1024];
__device__ __half g_dec16[8192 * 1024];
__device__ __half g_y1n16[8192 * 1024];
__device__ __half g_uhb[8192L * FFP_];

// ================= helpers =================
__device__ __forceinline__ uint32_t smem_u32(const void* p) {
    uint32_t a;
    asm("{ .reg .u64 t; cvta.to.shared.u64 t, %1; cvt.u32.u64 %0, t; }" : "=r"(a) : "l"(p));
    return a;
}

#define HROWB 80   // bytes per smem row: 32 halves (64B) + 16B pad

// fp16 K-chunk (32) tile loader
template <int ROWS, int THREADS>
__device__ __forceinline__ void tile_load_h(const __half* __restrict__ src, int rowBase, int rowLim,
                                            int lda, int Kd, int k0, uint32_t sdst, int tid) {
    if (k0 + 32 <= Kd) {
        #pragma unroll
        for (int t = tid; t < ROWS * 4; t += THREADS) {
            int r = t >> 2, ch = t & 3;
            uint32_t d = sdst + (uint32_t)(r * HROWB + ch * 16);
            int gr = rowBase + r;
            if (gr < rowLim) {
                const __half* g = src + (long)gr * lda + k0 + ch * 8;
                asm volatile("cp.async.cg.shared.global [%0], [%1], 16;" :: "r"(d), "l"(g));
            } else {
                asm volatile("st.shared.v4.b32 [%0], {%1,%1,%1,%1};" :: "r"(d), "r"(0));
            }
        }
    } else {
        #pragma unroll
        for (int t = tid; t < ROWS * 32; t += THREADS) {
            int r = t >> 5, k = t & 31;
            int gr = rowBase + r, gk = k0 + k;
            uint16_t v = 0;
            if (gr < rowLim && gk < Kd) v = __half_as_ushort(src[(long)gr * lda + gk]);
            uint32_t d = sdst + (uint32_t)(r * HROWB + k * 2);
            asm volatile("st.shared.u16 [%0], %1;" :: "r"(d), "h"(v));
        }
    }
}

#define CP_COMMIT() asm volatile("cp.async.commit_group;" ::: "memory")
#define CP_WAIT1()  asm volatile("cp.async.wait_group 1;" ::: "memory")
#define CP_WAIT0()  asm volatile("cp.async.wait_group 0;" ::: "memory")

#define MMA_F16(acc, a, b) \
    asm volatile("mma.sync.aligned.m16n8k16.row.col.f32.f16.f16.f32 " \
        "{%0,%1,%2,%3}, {%4,%5,%6,%7}, {%8,%9}, {%0,%1,%2,%3};" \
        : "+f"((acc)[0]), "+f"((acc)[1]), "+f"((acc)[2]), "+f"((acc)[3]) \
        : "r"((a)[0]), "r"((a)[1]), "r"((a)[2]), "r"((a)[3]), "r"((b)[0]), "r"((b)[1]))

#define LDSM_X4(r0, r1, r2, r3, addr) \
    asm volatile("ldmatrix.sync.aligned.m8n8.x4.shared.b16 {%0,%1,%2,%3}, [%4];" \
        : "=r"(r0), "=r"(r1), "=r"(r2), "=r"(r3) : "r"(addr))

// epilogue modes:
// 0 = f32 store (+bias); 1 = f32 addC (+bias); 2 = f16 store (ldD, +bias);
// 4 = paired swiglu: acc pair (u,g) at cols (n, n+1) -> silu(u)*g stored f16 at col n/2 (ldD)
__device__ __forceinline__ void epi_pair(int mode, void* D, int ldD,
                                         const float* bias, int N, long m, int n,
                                         float vx, float vy) {
    if (n >= N) return;
    if (bias) { vx += bias[n]; vy += bias[n + 1]; }
    if (mode == 0) {
        *(float2*)((float*)D + m * N + n) = make_float2(vx, vy);
    } else if (mode == 1) {
        float2* cp = (float2*)((float*)D + m * N + n);
        float2 o = *cp;
        *cp = make_float2(vx + o.x, vy + o.y);
    } else if (mode == 2) {
        *(__half2*)((__half*)D + m * ldD + n) = __floats2half2_rn(vx, vy);
    } else {
        float h = (vx / (1.f + expf(-vx))) * vy;
        *((__half*)D + m * ldD + (n >> 1)) = __float2half_rn(h);
    }
}

// ================= big GEMM: 128x128 tile, BK=32, 8 warps (2x4), warp 64x32 ==
#define BIG_TILE_B (128 * HROWB)
#define BIG_STAGE_B (2 * BIG_TILE_B)
#define BIG_SMEM_BYTES (3 * BIG_STAGE_B)

__global__ void __launch_bounds__(256) gemm_h16(const __half* __restrict__ A, int lda,
                                                const __half* __restrict__ Bw, int ldb,
                                                const float* __restrict__ bias, void* __restrict__ D,
                                                int ldD, int M, int N, int Kd, int mode) {
    extern __shared__ uint32_t smu[];
    const uint32_t sbase = smem_u32(smu);
    const int tid = threadIdx.x;
    const int wid = tid >> 5, lane = tid & 31;
    const int wm = wid & 1, wn = wid >> 1;
    const int bm = blockIdx.y * 128, bn = blockIdx.x * 128;
    const int lr = lane >> 2, lc = lane & 3;
    const uint32_t lrow = (lane & 15), lhi = (lane >> 4) << 4;

    float acc[4][4][4];
    #pragma unroll
    for (int i = 0; i < 4; i++)
        #pragma unroll
        for (int j = 0; j < 4; j++)
            #pragma unroll
            for (int e = 0; e < 4; e++) acc[i][j][e] = 0.f;

    const int NC = (Kd + 31) / 32;

    tile_load_h<128, 256>(A, bm, M, lda, Kd, 0, sbase, tid);
    tile_load_h<128, 256>(Bw, bn, N, ldb, Kd, 0, sbase + BIG_TILE_B, tid);
    CP_COMMIT();
    if (NC > 1) {
        tile_load_h<128, 256>(A, bm, M, lda, Kd, 32, sbase + BIG_STAGE_B, tid);
        tile_load_h<128, 256>(Bw, bn, N, ldb, Kd, 32, sbase + BIG_STAGE_B + BIG_TILE_B, tid);
        CP_COMMIT();
    }

    for (int c = 0; c < NC; c++) {
        if (c + 1 < NC) CP_WAIT1(); else CP_WAIT0();
        __syncthreads();
        if (c + 2 < NC) {
            uint32_t soff = sbase + (uint32_t)(((c + 2) % 3) * BIG_STAGE_B);
            tile_load_h<128, 256>(A, bm, M, lda, Kd, (c + 2) * 32, soff, tid);
            tile_load_h<128, 256>(Bw, bn, N, ldb, Kd, (c + 2) * 32, soff + BIG_TILE_B, tid);
            CP_COMMIT();
        }
        const uint32_t abase = sbase + (uint32_t)((c % 3) * BIG_STAGE_B);
        const uint32_t bbase = abase + BIG_TILE_B;
        #pragma unroll
        for (int ks = 0; ks < 2; ks++) {
            uint32_t afr[4][4], bfr[4][2];
            #pragma unroll
            for (int mi = 0; mi < 4; mi++) {
                uint32_t ad = abase + (wm * 64 + mi * 16 + lrow) * HROWB + ks * 32 + lhi;
                LDSM_X4(afr[mi][0], afr[mi][1], afr[mi][2], afr[mi][3], ad);
            }
            #pragma unroll
            for (int p = 0; p < 2; p++) {
                uint32_t e0, o0, e1, o1;
                uint32_t bd = bbase + (wn * 32 + p * 16 + lrow) * HROWB + ks * 32 + lhi;
                LDSM_X4(e0, o0, e1, o1, bd);
                bfr[2 * p][0] = e0; bfr[2 * p][1] = e1;
                bfr[2 * p + 1][0] = o0; bfr[2 * p + 1][1] = o1;
            }
            #pragma unroll
            for (int mi = 0; mi < 4; mi++)
                #pragma unroll
                for (int ni = 0; ni < 4; ni++)
                    MMA_F16(acc[mi][ni], afr[mi], bfr[ni]);
        }
    }

    #pragma unroll
    for (int mi = 0; mi < 4; mi++) {
        #pragma unroll
        for (int ni = 0; ni < 4; ni++) {
            long m0 = bm + wm * 64 + mi * 16 + lr;
            int n0 = bn + wn * 32 + ni * 8 + 2 * lc;
            epi_pair(mode, D, ldD, bias, N, m0, n0, acc[mi][ni][0], acc[mi][ni][1]);
            epi_pair(mode, D, ldD, bias, N, m0 + 8, n0, acc[mi][ni][2], acc[mi][ni][3]);
        }
    }
}

// ===== small GEMM: 64x64 tile, BK=32, 256 threads (8 warps 2x4), warp 32x16 ==
#define SM_TILE_B (64 * HROWB)
#define SM_STAGE_B (2 * SM_TILE_B)
#define SM_SMEM_BYTES (3 * SM_STAGE_B)

__global__ void __launch_bounds__(256) gemm_h16_s(const __half* __restrict__ A, int lda,
                                                  const __half* __restrict__ Bw, int ldb,
                                                  const float* __restrict__ bias, void* __restrict__ D,
                                                  int ldD, int M, int N, int Kd, int mode) {
    extern __shared__ uint32_t smu[];
    const uint32_t sbase = smem_u32(smu);
    const int tid = threadIdx.x;
    const int wid = tid >> 5, lane = tid & 31;
    const int wm = wid & 1, wn = wid >> 1;           // 2 (M) x 4 (N)
    const int bm = blockIdx.y * 64, bn = blockIdx.x * 64;
    const int lr = lane >> 2, lc = lane & 3;
    const uint32_t lrow = (lane & 15), lhi = (lane >> 4) << 4;

    float acc[2][2][4];
    #pragma unroll
    for (int i = 0; i < 2; i++)
        #pragma unroll
        for (int j = 0; j < 2; j++)
            #pragma unroll
            for (int e = 0; e < 4; e++) acc[i][j][e] = 0.f;

    const int NC = (Kd + 31) / 32;

    tile_load_h<64, 256>(A, bm, M, lda, Kd, 0, sbase, tid);
    tile_load_h<64, 256>(Bw, bn, N, ldb, Kd, 0, sbase + SM_TILE_B, tid);
    CP_COMMIT();
    if (NC > 1) {
        tile_load_h<64, 256>(A, bm, M, lda, Kd, 32, sbase + SM_STAGE_B, tid);
        tile_load_h<64, 256>(Bw, bn, N, ldb, Kd, 32, sbase + SM_STAGE_B + SM_TILE_B, tid);
        CP_COMMIT();
    }

    for (int c = 0; c < NC; c++) {
        if (c + 1 < NC) CP_WAIT1(); else CP_WAIT0();
        __syncthreads();
        if (c + 2 < NC) {
            uint32_t soff = sbase + (uint32_t)(((c + 2) % 3) * SM_STAGE_B);
            tile_load_h<64, 256>(A, bm, M, lda, Kd, (c + 2) * 32, soff, tid);
            tile_load_h<64, 256>(Bw, bn, N, ldb, Kd, (c + 2) * 32, soff + SM_TILE_B, tid);
            CP_COMMIT();
        }
        const uint32_t abase = sbase + (uint32_t)((c % 3) * SM_STAGE_B);
        const uint32_t bbase = abase + SM_TILE_B;
        #pragma unroll
        for (int ks = 0; ks < 2; ks++) {
            uint32_t afr[2][4], bfr[2][2];
            #pragma unroll
            for (int mi = 0; mi < 2; mi++) {
                uint32_t ad = abase + (wm * 32 + mi * 16 + lrow) * HROWB + ks * 32 + lhi;
                LDSM_X4(afr[mi][0], afr[mi][1], afr[mi][2], afr[mi][3], ad);
            }
            {
                uint32_t e0, o0, e1, o1;
                uint32_t bd = bbase + (wn * 16 + lrow) * HROWB + ks * 32 + lhi;
                LDSM_X4(e0, o0, e1, o1, bd);
                bfr[0][0] = e0; bfr[0][1] = e1;
                bfr[1][0] = o0; bfr[1][1] = o1;
            }
            #pragma unroll
            for (int mi = 0; mi < 2; mi++)
                #pragma unroll
                for (int ni = 0; ni < 2; ni++)
                    MMA_F16(acc[mi][ni], afr[mi], bfr[ni]);
        }
    }

    #pragma unroll
    for (int mi = 0; mi < 2; mi++) {
        #pragma unroll
        for (int ni = 0; ni < 2; ni++) {
            long m0 = bm + wm * 32 + mi * 16 + lr;
            int n0 = bn + wn * 16 + ni * 8 + 2 * lc;
            if (m0 < M) {
                epi_pair(mode, D, ldD, bias, N, m0, n0, acc[mi][ni][0], acc[mi][ni][1]);
                epi_pair(mode, D, ldD, bias, N, m0 + 8, n0, acc[mi][ni][2], acc[mi][ni][3]);
            }
        }
    }
}

// ---------------- conversions ----------------
__global__ void convert_f2h4(const float4* __restrict__ src, __half2* __restrict__ dst, long n4) {
    long stride = (long)gridDim.x * blockDim.x;
    for (long i = (long)blockIdx.x * blockDim.x + threadIdx.x; i < n4; i += stride) {
        float4 v = src[i];
        dst[2 * i]     = __floats2half2_rn(v.x, v.y);
        dst[2 * i + 1] = __floats2half2_rn(v.z, v.w);
    }
}
__global__ void convert_f2h_pad2(const float2* __restrict__ src, __half2* __restrict__ dst,
                                 int rows, int Kc2, int ldd2) {
    int r = blockIdx.x;
    const float2* srow = src + (long)r * Kc2;
    __half2* drow = dst + (long)r * ldd2;
    for (int c = threadIdx.x; c < Kc2; c += blockDim.x) {
        float2 v = srow[c];
        drow[c] = __floats2half2_rn(v.x, v.y);
    }
}
// interleave: dst row 2j = w1 row j, dst row 2j+1 = w3 row j.  K = 1024
__global__ void convert_inter(const float4* __restrict__ w1, const float4* __restrict__ w3,
                              __half2* __restrict__ dst, long rows) {
    long n = rows * 256;
    long stride = (long)gridDim.x * blockDim.x;
    for (long i = (long)blockIdx.x * blockDim.x + threadIdx.x; i < n; i += stride) {
        long r = i >> 8;
        int c = (int)(i & 255);
        float4 a = w1[i];
        float4 b = w3[i];
        __half2* d1 = dst + (2 * r) * 512 + 2 * c;
        __half2* d3 = dst + (2 * r + 1) * 512 + 2 * c;
        d1[0] = __floats2half2_rn(a.x, a.y);
        d1[1] = __floats2half2_rn(a.z, a.w);
        d3[0] = __floats2half2_rn(b.x, b.y);
        d3[1] = __floats2half2_rn(b.z, b.w);
    }
}

// ---------------- block reduce ----------------
__device__ __forceinline__ float blockReduceSum(float v) {
    __shared__ float sh[33];
    int lane = threadIdx.x & 31, wid = threadIdx.x >> 5;
    #pragma unroll
    for (int o = 16; o; o >>= 1) v += __shfl_xor_sync(0xFFFFFFFFu, v, o);
    if (lane == 0) sh[wid] = v;
    __syncthreads();
    int nw = blockDim.x >> 5;
    v = (threadIdx.x < nw) ? sh[lane] : 0.f;
    if (wid == 0) {
        #pragma unroll
        for (int o = 16; o; o >>= 1) v += __shfl_xor_sync(0xFFFFFFFFu, v, o);
        if (lane == 0) sh[32] = v;
    }
    __syncthreads();
    return sh[32];
}

// ---------------- sort + gather / unsort ----------------
__global__ void sort_gather_kernel(const float* __restrict__ cw,
                                   const float* __restrict__ repr,
                                   float* __restrict__ x, int* __restrict__ sidx) {
    int b = blockIdx.x, tid = threadIdx.x;
    __shared__ float w[64];
    __shared__ int pos[64];
    if (tid < 64) w[tid] = cw[b * 64 + tid];
    __syncthreads();
    if (tid < 64) {
        float wi = w[tid];
        int r = 0;
        for (int j = 0; j < 64; j++) {
            float wj = w[j];
            if (wj > wi || (wj == wi && j < tid)) r++;
        }
        pos[r] = tid;
        sidx[b * 64 + r] = tid;
    }
    __syncthreads();
    for (int t = tid; t < 64 * 256; t += blockDim.x) {
        int k = t >> 8, c4 = t & 255;
        const float4* s = (const float4*)(repr + ((long)b * 64 + pos[k]) * 1024) + c4;
        *((float4*)(x + ((long)b * 64 + k) * 1024) + c4) = *s;
    }
}

__global__ void unsort_h_kernel(const float* __restrict__ x, const int* __restrict__ sidx,
                                __half* __restrict__ proc) {
    int b = blockIdx.x, tid = threadIdx.x;
    __shared__ int pos[64];
    if (tid < 64) pos[tid] = sidx[b * 64 + tid];
    __syncthreads();
    for (int t = tid; t < 64 * 256; t += blockDim.x) {
        int k = t >> 8, c4 = t & 255;
        float4 v = *((const float4*)(x + ((long)b * 64 + k) * 1024) + c4);
        __half2* d = (__half2*)(proc + ((long)b * 64 + pos[k]) * 1024) + 2 * c4;
        d[0] = __floats2half2_rn(v.x, v.y);
        d[1] = __floats2half2_rn(v.z, v.w);
    }
}

// ---------------- RMS (fp32 in -> fp16 out) ----------------
__global__ void rms16_kernel(const float* __restrict__ x, const float* __restrict__ w,
                             __half* __restrict__ out) {
    long row = blockIdx.x;
    const float* xr = x + row * H_;
    float s = 0.f;
    for (int i = threadIdx.x; i < H_; i += blockDim.x) { float v = xr[i]; s += v * v; }
    float tot = blockReduceSum(s);
    float scale = rsqrtf(tot * (1.0f / H_) + 1e-6f);
    for (int i = threadIdx.x; i < H_; i += blockDim.x)
        out[row * H_ + i] = __float2half_rn(xr[i] * scale * w[i]);
}

// fused: y1 = rms(a+b, w1) -> out (fp32); y2 = rms(y1, w2) -> y16 (fp16)
__global__ void add_rms2_kernel(const float* __restrict__ a, const float* __restrict__ bsrc,
                                const float* __restrict__ w1, const float* __restrict__ w2,
                                float* __restrict__ out, __half* __restrict__ y16) {
    long row = blockIdx.x;
    __shared__ float buf[H_];
    float s = 0.f;
    for (int i = threadIdx.x; i < H_; i += blockDim.x) {
        float v = a[row * H_ + i] + bsrc[row * H_ + i];
        buf[i] = v;
        s += v * v;
    }
    float tot = blockReduceSum(s);
    float sc1 = rsqrtf(tot * (1.0f / H_) + 1e-6f);
    float s2 = 0.f;
    for (int i = threadIdx.x; i < H_; i += blockDim.x) {
        float y1 = buf[i] * sc1 * w1[i];
        out[row * H_ + i] = y1;
        s2 += y1 * y1;
    }
    float tot2 = blockReduceSum(s2);
    float sc2 = rsqrtf(tot2 * (1.0f / H_) + 1e-6f);
    for (int i = threadIdx.x; i < H_; i += blockDim.x) {
        float y1 = buf[i] * sc1 * w1[i];
        y16[row * H_ + i] = __float2half_rn(y1 * sc2 * w2[i]);
    }
}

// ---------------- cascade self-attention (causal, K=64, d=64) --------------
#define KST 65
#define CASC_SMEM (4 * 64 * KST * 4)
__global__ void casc_attn_kernel(const float* __restrict__ qkv, __half* __restrict__ att) {
    int h = blockIdx.x, b = blockIdx.y;
    extern __shared__ float cs[];
    float* Qs = cs;
    float* Ks = cs + 64 * KST;
    float* Vs = cs + 2 * 64 * KST;
    float* Ps = cs + 3 * 64 * KST;
    const float* base = qkv + (long)b * 64 * 3072;
    int tid = threadIdx.x;
    for (int t = tid; t < 4096; t += 256) {
        int r = t >> 6, j = t & 63;
        const float* src = base + r * 3072 + h * 64 + j;
        Qs[r * KST + j] = src[0];
        Ks[r * KST + j] = src[1024];
        Vs[r * KST + j] = src[2048];
    }
    __syncthreads();
    int i = tid >> 2;
    int jg = (tid & 3) * 16;
    float sc[16];
    #pragma unroll
    for (int jj = 0; jj < 16; jj++) sc[jj] = 0.f;
    for (int k = 0; k < 64; k++) {
        float qv = Qs[i * KST + k];
        #pragma unroll
        for (int jj = 0; jj < 16; jj++) sc[jj] = fmaf(qv, Ks[(jg + jj) * KST + k], sc[jj]);
    }
    float mx = -1e30f;
    #pragma unroll
    for (int jj = 0; jj < 16; jj++) {
        int j = jg + jj;
        sc[jj] = (j <= i) ? sc[jj] * 0.125f : -1e30f;
        mx = fmaxf(mx, sc[jj]);
    }
    mx = fmaxf(mx, __shfl_xor_sync(0xFFFFFFFFu, mx, 1));
    mx = fmaxf(mx, __shfl_xor_sync(0xFFFFFFFFu, mx, 2));
    float e[16];
    float sum = 0.f;
    #pragma unroll
    for (int jj = 0; jj < 16; jj++) {
        int j = jg + jj;
        e[jj] = (j <= i) ? expf(sc[jj] - mx) : 0.f;
        sum += e[jj];
    }
    sum += __shfl_xor_sync(0xFFFFFFFFu, sum, 1);
    sum += __shfl_xor_sync(0xFFFFFFFFu, sum, 2);
    float inv = 1.f / sum;
    #pragma unroll
    for (int jj = 0; jj < 16; jj++) Ps[i * KST + jg + jj] = e[jj] * inv;
    __syncthreads();
    float o[16];
    #pragma unroll
    for (int jj = 0; jj < 16; jj++) o[jj] = 0.f;
    for (int k = 0; k < 64; k++) {
        float p = Ps[i * KST + k];
        #pragma unroll
        for (int jj = 0; jj < 16; jj++) o[jj] = fmaf(p, Vs[k * KST + jg + jj], o[jj]);
    }
    __half* orow = att + (long)(b * 64 + i) * 1024 + h * 64;
    #pragma unroll
    for (int jj = 0; jj < 16; jj++) orow[jg + jj] = __float2half_rn(o[jj]);
}

// ---------------- decoder cross-attention (Q fp16) ------------------------
__global__ void dec_attn_kernel(const __half* __restrict__ Qh, const float* __restrict__ Kc,
                                const float* __restrict__ Vc, __half* __restrict__ O) {
    int h = blockIdx.y, b = blockIdx.z;
    __shared__ float Ks[64][65];
    __shared__ float Vs[64][65];
    __shared__ float Qs[32][68];
    __shared__ float Pw[8][64];
    int tid = threadIdx.x;
    int s0 = blockIdx.x * 32;
    for (int t = tid; t < 4096; t += 256) {
        int r = t >> 6, j = t & 63;
        Ks[r][j] = Kc[(long)(b * 64 + r) * 1024 + h * 64 + j];
        Vs[r][j] = Vc[(long)(b * 64 + r) * 1024 + h * 64 + j];
    }
    for (int t = tid; t < 1024; t += 256) {
        int r = t >> 5, j2 = (t & 31) * 2;
        __half2 v = *(const __half2*)(Qh + ((long)b * S_ + s0 + r) * 1024 + h * 64 + j2);
        Qs[r][j2] = __half2float(v.x);
        Qs[r][j2 + 1] = __half2float(v.y);
    }
    __syncthreads();
    int warp = tid >> 5, lane = tid & 31;
    for (int qi = 0; qi < 4; qi++) {
        int lrq = warp * 4 + qi;
        int s = s0 + lrq;
        int lim = s / 32 + 1;
        if (lim > 63) lim = 63;
        float sc0 = 0.f, sc1 = 0.f;
        for (int k = 0; k < 64; k++) {
            float qv = Qs[lrq][k];
            sc0 = fmaf(qv, Ks[lane][k], sc0);
            sc1 = fmaf(qv, Ks[lane + 32][k], sc1);
        }
        sc0 *= 0.125f;
        sc1 *= 0.125f;
        bool a0 = lane <= lim, a1 = (lane + 32) <= lim;
        float m = fmaxf(a0 ? sc0 : -1e30f, a1 ? sc1 : -1e30f);
        #pragma unroll
        for (int o = 16; o; o >>= 1) m = fmaxf(m, __shfl_xor_sync(0xFFFFFFFFu, m, o));
        float e0 = a0 ? expf(sc0 - m) : 0.f;
        float e1 = a1 ? expf(sc1 - m) : 0.f;
        float sum = e0 + e1;
        #pragma unroll
        for (int o = 16; o; o >>= 1) sum += __shfl_xor_sync(0xFFFFFFFFu, sum, o);
        float inv = 1.f / sum;
        Pw[warp][lane] = e0 * inv;
        Pw[warp][lane + 32] = e1 * inv;
        __syncwarp();
        float o0 = 0.f, o1 = 0.f;
        for (int k = 0; k <= lim; k++) {
            float p = Pw[warp][k];
            o0 = fmaf(p, Vs[k][lane], o0);
            o1 = fmaf(p, Vs[k][lane + 32], o1);
        }
        __half* orow = O + ((long)b * S_ + s) * 1024 + h * 64;
        orow[lane] = __float2half_rn(o0);
        orow[lane + 32] = __float2half_rn(o1);
        __syncwarp();
    }
}

// ---------------- host launch ---------------------------------------------
static void gemm_h(cudaStream_t st, const __half* A, int lda, const __half* Bw, int ldb,
                   const float* bias, void* D, int ldD, int M, int N, int Kd, int mode) {
    if (M <= 256) {
        dim3 g((N + 63) / 64, (M + 63) / 64);
        gemm_h16_s<<<g, 256, SM_SMEM_BYTES, st>>>(A, lda, Bw, ldb, bias, D, ldD, M, N, Kd, mode);
    } else {
        dim3 g((N + 127) / 128, (M + 127) / 128);
        gemm_h16<<<g, 256, BIG_SMEM_BYTES, st>>>(A, lda, Bw, ldb, bias, D, ldD, M, N, Kd, mode);
    }
}

extern "C" void kernel_launch(void* const* d_in, const int* in_sizes, int n_in,
                              void* d_out, int out_size) {
    const float* token        = (const float*)d_in[0];
    const float* chunk_repr   = (const float*)d_in[1];
    const float* chunk_w      = (const float*)d_in[2];
    const float* casc_norm1   = (const float*)d_in[3];
    const float* casc_qkv     = (const float*)d_in[4];
    const float* casc_o       = (const float*)d_in[5];
    const float* casc_norm2   = (const float*)d_in[6];
    const float* casc_w1      = (const float*)d_in[7];
    const float* casc_w2      = (const float*)d_in[8];
    const float* casc_w3      = (const float*)d_in[9];
    const float* dec_in_w     = (const float*)d_in[10];
    const float* dec_in_b     = (const float*)d_in[11];
    const float* dec_out_w    = (const float*)d_in[12];
    const float* dec_out_b    = (const float*)d_in[13];
    const float* dec_norm_w   = (const float*)d_in[14];
    const float* dec_ffn_norm = (const float*)d_in[15];
    const float* dec_w1       = (const float*)d_in[16];
    const float* dec_w2       = (const float*)d_in[17];
    const float* dec_w3       = (const float*)d_in[18];
    float* out = (float*)d_out;

    cudaFuncSetAttribute(gemm_h16, cudaFuncAttributeMaxDynamicSharedMemorySize, BIG_SMEM_BYTES);
    cudaFuncSetAttribute(gemm_h16_s, cudaFuncAttributeMaxDynamicSharedMemorySize, SM_SMEM_BYTES);
    cudaFuncSetAttribute(casc_attn_kernel, cudaFuncAttributeMaxDynamicSharedMemorySize, CASC_SMEM);

    float *px, *pqkv, *pq, *pkk, *pvv;
    int* psidx;
    __half *pw, *pq16, *pph, *ppatt, *puhs, *pproc16, *pdec16, *py1n16, *puhb;
    cudaGetSymbolAddress((void**)&px, g_x);
    cudaGetSymbolAddress((void**)&pqkv, g_qkv);
    cudaGetSymbolAddress((void**)&pq, g_q);
    cudaGetSymbolAddress((void**)&pkk, g_kk);
    cudaGetSymbolAddress((void**)&pvv, g_vv);
    cudaGetSymbolAddress((void**)&psidx, g_sidx);
    cudaGetSymbolAddress((void**)&pw, g_w16);
    cudaGetSymbolAddress((void**)&pq16, g_q16);
    cudaGetSymbolAddress((void**)&pph, g_ph);
    cudaGetSymbolAddress((void**)&ppatt, g_patt);
    cudaGetSymbolAddress((void**)&puhs, g_uhs);
    cudaGetSymbolAddress((void**)&pproc16, g_proc16);
    cudaGetSymbolAddress((void**)&pdec16, g_dec16);
    cudaGetSymbolAddress((void**)&py1n16, g_y1n16);
    cudaGetSymbolAddress((void**)&puhb, g_uhb);

    // ---- fp16 weight layout (interleaved w1/w3) ----
    const long o_cqkv = 0;
    const long o_co   = o_cqkv + 2L * 3072 * 1024;
    const long o_cw13 = o_co   + 2L * 1024 * 1024;
    const long o_cw2  = o_cw13 + 2L * FF2_ * 1024;
    const long o_din  = o_cw2  + 2L * 1024 * FFP_;
    const long o_dout = o_din  + 3L * 1024 * 1024;
    const long o_dw13 = o_dout + 1024L * 1024;
    const long o_dw2  = o_dw13 + (long)FF2_ * 1024;
    const long o_tok  = o_dw2  + 1024L * FFP_;
    const __half* tok16 = pw + o_tok;

    // ---- stream fork ----
    cudaStream_t s1;
    cudaStreamCreateWithFlags(&s1, cudaStreamNonBlocking);
    cudaEvent_t ev0, ev1;
    cudaEventCreateWithFlags(&ev0, cudaEventDisableTiming);
    cudaEventCreateWithFlags(&ev1, cudaEventDisableTiming);
    cudaEventRecord(ev0, 0);
    cudaStreamWaitEvent(s1, ev0, 0);

    // side stream: decoder prep + Q projection (fp16 out)
    convert_f2h4<<<2048, 256, 0, s1>>>((const float4*)token, (__half2*)(pw + o_tok), 8192L * 256);
    convert_f2h4<<<1024, 256, 0, s1>>>((const float4*)dec_in_w, (__half2*)(pw + o_din), 3L * 256 * 1024);
    convert_f2h4<<<512, 256, 0, s1>>>((const float4*)dec_out_w, (__half2*)(pw + o_dout), 256L * 1024);
    convert_inter<<<1024, 256, 0, s1>>>((const float4*)dec_w1, (const float4*)dec_w3,
                                        (__half2*)(pw + o_dw13), FF_);
    convert_f2h_pad2<<<1024, 256, 0, s1>>>((const float2*)dec_w2, (__half2*)(pw + o_dw2), 1024, FF_ / 2, FFP_ / 2);
    gemm_h(s1, tok16, 1024, pw + o_din, 1024, dec_in_b, pq16, 1024, B_ * S_, 1024, 1024, 2);  // Q proj fp16
    cudaEventRecord(ev1, s1);

    // main stream: cascade weights + cascade pipeline
    convert_f2h4<<<1024, 256>>>((const float4*)casc_qkv, (__half2*)(pw + o_cqkv), 2L * 3072 * 256);
    convert_f2h4<<<512, 256>>>((const float4*)casc_o, (__half2*)(pw + o_co), 2L * 256 * 1024);
    convert_inter<<<1024, 256>>>((const float4*)casc_w1, (const float4*)casc_w3,
                                 (__half2*)(pw + o_cw13), 2L * FF_);
    convert_f2h_pad2<<<2048, 256>>>((const float2*)casc_w2, (__half2*)(pw + o_cw2), 2 * 1024, FF_ / 2, FFP_ / 2);

    sort_gather_kernel<<<B_, 256>>>(chunk_w, chunk_repr, px, psidx);

    for (int l = 0; l < L_; l++) {
        rms16_kernel<<<256, 256>>>(px, casc_norm1 + (long)l * H_, pph);
        gemm_h(0, pph, 1024, pw + o_cqkv + (long)l * 3072 * 1024, 1024, nullptr, pqkv, 0, 256, 3072, 1024, 0);
        casc_attn_kernel<<<dim3(NH_, B_), 256, CASC_SMEM>>>(pqkv, ppatt);
        gemm_h(0, ppatt, 1024, pw + o_co + (long)l * 1024 * 1024, 1024, nullptr, px, 0, 256, 1024, 1024, 1);
        rms16_kernel<<<256, 256>>>(px, casc_norm2 + (long)l * H_, pph);
        gemm_h(0, pph, 1024, pw + o_cw13 + (long)l * FF2_ * 1024, 1024, nullptr, puhs, FFP_, 256, FF2_, 1024, 4);
        gemm_h(0, puhs, FFP_, pw + o_cw2 + (long)l * 1024 * FFP_, FFP_, nullptr, px, 0, 256, 1024, FF_, 1);
    }

    unsort_h_kernel<<<B_, 256>>>(px, psidx, pproc16);

    cudaStreamWaitEvent(0, ev1, 0);
    gemm_h(0, pproc16, 1024, pw + o_din + 1024L * 1024, 1024, dec_in_b + 1024, pkk, 0, 256, 1024, 1024, 0);
    gemm_h(0, pproc16, 1024, pw + o_din + 2L * 1024 * 1024, 1024, dec_in_b + 2048, pvv, 0, 256, 1024, 1024, 0);
    dec_attn_kernel<<<dim3(S_ / 32, NH_, B_), 256>>>(pq16, pkk, pvv, pdec16);
    gemm_h(0, pdec16, 1024, pw + o_dout, 1024, dec_out_b, pq, 0, B_ * S_, 1024, 1024, 0);     // out proj
    add_rms2_kernel<<<B_ * S_, 256>>>(token, pq, dec_norm_w, dec_ffn_norm, out, py1n16);
    gemm_h(0, py1n16, 1024, pw + o_dw13, 1024, nullptr, puhb, FFP_, B_ * S_, FF2_, 1024, 4);  // fused w1/w3+swiglu
    gemm_h(0, puhb, FFP_, pw + o_dw2, FFP_, nullptr, out, 0, B_ * S_, 1024, FF_, 1);          // y = y1 + ffn
}